// round 14
// baseline (speedup 1.0000x reference)
#include <cuda_runtime.h>
#include <cuda_bf16.h>
#include <math.h>
#include <cstdint>

// Problem constants
#define BB   4
#define SEQ  2048
#define DD   1024
#define GG   256
#define QKD  128
#define HHID 2048
#define MROWS (BB*SEQ)        // 8192
#define NGRP  (MROWS/GG)      // 32
#define TWOH  (2*HHID)        // 4096
#define LDH   4352            // h|qk|pad row stride (17 * 256)
#define QKOFF 4096            // qk column offset inside LDH
#define NCAT  4352

// -------- device scratch (no cudaMalloc allowed) --------
__device__ __nv_bfloat16 g_normed_bf[(size_t)MROWS*DD];    // 16 MB
__device__ __nv_bfloat16 g_hq_bf[(size_t)MROWS*LDH];       // 71 MB (v | gate | qk | pad)
__device__ __nv_bfloat16 g_quadq_bf[(size_t)MROWS*QKD];    // 2 MB
__device__ __nv_bfloat16 g_quadk_bf[(size_t)MROWS*QKD];    // 2 MB
__device__ __nv_bfloat16 g_linq_bf[(size_t)MROWS*QKD];     // 2 MB
__device__ __nv_bfloat16 g_linkT_bf[(size_t)BB*QKD*SEQ];   // 2 MB  lin_k^T [b][d][n]
__device__ __nv_bfloat16 g_attn_bf[(size_t)NGRP*GG*GG];    // 4 MB
__device__ __nv_bfloat16 g_linkv_bf[(size_t)BB*QKD*HHID];  // 2 MB
__device__ __nv_bfloat16 g_gated_bf[(size_t)MROWS*HHID];   // 32 MB
__device__ __nv_bfloat16 g_wcatT[(size_t)NCAT*DD];         // 8.9 MB  [W_hidden|W_qk|0]^T
__device__ __nv_bfloat16 g_woT[(size_t)DD*HHID];           // 4 MB
__device__ float g_bcat[NCAT];
__device__ float g_sin[SEQ*64];
__device__ float g_cos[SEQ*64];

// =================== PTX helpers (arch-portable: sm_80+ subset) ===================
__device__ __forceinline__ uint32_t smem_u32(const void* p) {
    uint32_t a;
    asm("{ .reg .u64 t; cvta.to.shared.u64 t, %1; cvt.u32.u64 %0, t; }" : "=r"(a) : "l"(p));
    return a;
}
#define SW128(o) ((o) ^ (((o) >> 3) & 0x70))   // 128B rows
#define SWZ256(o) ((o) ^ (((o) >> 4) & 0x70))  // 256B rows

__device__ __forceinline__ void cpa16(uint32_t dst, const void* src) {
    asm volatile("cp.async.cg.shared.global [%0], [%1], 16;" :: "r"(dst), "l"(src));
}
#define CP_COMMIT() asm volatile("cp.async.commit_group;" ::: "memory")
#define CP_WAIT(n)  asm volatile("cp.async.wait_group %0;" :: "n"(n) : "memory")

__device__ __forceinline__ void ldsm_x4(uint32_t* r, uint32_t addr) {
    asm volatile("ldmatrix.sync.aligned.m8n8.x4.shared.b16 {%0,%1,%2,%3}, [%4];"
                 : "=r"(r[0]), "=r"(r[1]), "=r"(r[2]), "=r"(r[3]) : "r"(addr));
}
__device__ __forceinline__ void ldsm_x2(uint32_t* r, uint32_t addr) {
    asm volatile("ldmatrix.sync.aligned.m8n8.x2.shared.b16 {%0,%1}, [%2];"
                 : "=r"(r[0]), "=r"(r[1]) : "r"(addr));
}
__device__ __forceinline__ void ldsm_x4t(uint32_t* r, uint32_t addr) {
    asm volatile("ldmatrix.sync.aligned.m8n8.x4.trans.shared.b16 {%0,%1,%2,%3}, [%4];"
                 : "=r"(r[0]), "=r"(r[1]), "=r"(r[2]), "=r"(r[3]) : "r"(addr));
}
__device__ __forceinline__ void mma_16816(float* c, const uint32_t* a, const uint32_t* b) {
    asm volatile(
        "mma.sync.aligned.m16n8k16.row.col.f32.bf16.bf16.f32 "
        "{%0,%1,%2,%3}, {%4,%5,%6,%7}, {%8,%9}, {%0,%1,%2,%3};"
        : "+f"(c[0]), "+f"(c[1]), "+f"(c[2]), "+f"(c[3])
        : "r"(a[0]), "r"(a[1]), "r"(a[2]), "r"(a[3]), "r"(b[0]), "r"(b[1]));
}
__device__ __forceinline__ void st_bf2(__nv_bfloat16* p, float a, float b) {
    *(__nv_bfloat162*)p = __floats2bfloat162_rn(a, b);
}

// ====== bf16 tensor-core GEMM: C[M,N] = A[M,K] @ Bt[N,K]^T ======
// CTA tile 128 x 256, 8 warps (2x4), warp tile 64x64.
// 4-stage cp.async ring, ONE barrier per stage, B frags via ldmatrix.x4 pairs.
template<int K_TOT, bool SILU_, bool RESID_, bool OUTBF_>
__global__ void __launch_bounds__(256, 1)
mm_bf16_kernel(const __nv_bfloat16* __restrict__ A,
               const __nv_bfloat16* __restrict__ Bt,
               const float* __restrict__ bias,
               const float* __restrict__ resid,
               float* __restrict__ Cf, __nv_bfloat16* __restrict__ Cb, int ldC)
{
    constexpr int STAGES = K_TOT / 64;
    constexpr int A_B    = 128 * 128;       // 16 KB
    constexpr int B_B    = 256 * 128;       // 32 KB
    extern __shared__ char smem[];
    const uint32_t aB = smem_u32(smem);
    const uint32_t bB = aB + 4 * A_B;

    const int tid = threadIdx.x, wid = tid >> 5, lane = tid & 31;
    const int m0 = blockIdx.y * 128, n0 = blockIdx.x * 256;
    const int wm = (wid >> 2) * 64;
    const int wn = (wid & 3) * 64;

    auto loadA = [&](int s, int buf) {
        uint32_t base = aB + buf * A_B;
        const __nv_bfloat16* src = A + (size_t)m0 * K_TOT + s * 64;
#pragma unroll
        for (int i = 0; i < 4; i++) {
            int c = tid + i * 256;
            int row = c >> 3, col = c & 7;
            cpa16(base + SW128(row * 128 + col * 16), src + (size_t)row * K_TOT + col * 8);
        }
    };
    auto loadB = [&](int s, int buf) {
        uint32_t base = bB + buf * B_B;
        const __nv_bfloat16* src = Bt + (size_t)n0 * K_TOT + s * 64;
#pragma unroll
        for (int i = 0; i < 8; i++) {
            int c = tid + i * 256;
            int row = c >> 3, col = c & 7;
            cpa16(base + SW128(row * 128 + col * 16), src + (size_t)row * K_TOT + col * 8);
        }
    };

    float acc[4][8][4] = {};
    const int a_row = wm + (lane & 15);
    const int a_kof = (lane >> 4) * 8;
    // B via x4: lane group g = lane>>3 selects (n-half, k-half) of a 16x16 block
    const int bq_ro = (lane >> 4) * 8 + (lane & 7);    // (g>>1)*8 + r
    const int bq_ko = ((lane >> 3) & 1) * 8;           // (g&1)*8

    loadA(0, 0); loadB(0, 0); CP_COMMIT();
    loadA(1, 1); loadB(1, 1); CP_COMMIT();
    loadA(2, 2); loadB(2, 2); CP_COMMIT();

    for (int s = 0; s < STAGES; s++) {
        const int rem = STAGES - 1 - s;
        if (rem >= 2) CP_WAIT(2);
        else if (rem == 1) CP_WAIT(1);
        else CP_WAIT(0);
        __syncthreads();                       // stage s visible + buf (s-1)&3 free
        if (s + 3 < STAGES) { loadA(s + 3, (s + 3) & 3); loadB(s + 3, (s + 3) & 3); CP_COMMIT(); }
        const uint32_t abase = aB + (s & 3) * A_B;
        const uint32_t bbase = bB + (s & 3) * B_B;
#pragma unroll
        for (int ks = 0; ks < 4; ks++) {
            uint32_t af[4][4];
#pragma unroll
            for (int mi = 0; mi < 4; mi++)
                ldsm_x4(af[mi], abase + SW128((a_row + mi * 16) * 128 + (ks * 16 + a_kof) * 2));
            uint32_t bq[4][4];
#pragma unroll
            for (int nn = 0; nn < 4; nn++) {
                int row = wn + nn * 16 + bq_ro;
                int k   = ks * 16 + bq_ko;
                ldsm_x4(bq[nn], bbase + SW128(row * 128 + k * 2));
            }
#pragma unroll
            for (int mi = 0; mi < 4; mi++)
#pragma unroll
                for (int nn = 0; nn < 4; nn++) {
                    mma_16816(acc[mi][2 * nn + 0], af[mi], &bq[nn][0]);
                    mma_16816(acc[mi][2 * nn + 1], af[mi], &bq[nn][2]);
                }
        }
    }
    __syncthreads();

    const int er = m0 + wm + (lane >> 2);
    const int ec = n0 + wn + (lane & 3) * 2;
#pragma unroll
    for (int mi = 0; mi < 4; mi++)
#pragma unroll
        for (int ni = 0; ni < 8; ni++) {
            int col = ec + ni * 8;
#pragma unroll
            for (int half = 0; half < 2; half++) {
                int row = er + mi * 16 + half * 8;
                float v0 = acc[mi][ni][half * 2 + 0] + bias[col + 0];
                float v1 = acc[mi][ni][half * 2 + 1] + bias[col + 1];
                if (SILU_) { v0 = v0 / (1.0f + expf(-v0)); v1 = v1 / (1.0f + expf(-v1)); }
                if (RESID_) {
                    v0 += resid[(size_t)row * ldC + col + 0];
                    v1 += resid[(size_t)row * ldC + col + 1];
                }
                if (OUTBF_) st_bf2(Cb + (size_t)row * ldC + col, v0, v1);
                else { float2 o; o.x = v0; o.y = v1; *(float2*)(Cf + (size_t)row * ldC + col) = o; }
            }
        }
}

// ====== attn HMMA: attn = relu(quad_q @ quad_k^T / g)^2 -> bf16  (128x128 tile) ======
__global__ void __launch_bounds__(256)
attn_hmma_kernel()
{
    constexpr int TILE_B = 128 * 128;
    extern __shared__ char smem[];
    const uint32_t aB = smem_u32(smem);
    const uint32_t bB = aB + 2 * TILE_B;

    const int tid = threadIdx.x, wid = tid >> 5, lane = tid & 31;
    const int gid = blockIdx.z;
    const int i0 = blockIdx.y * 128, j0 = blockIdx.x * 128;
    const int wm = (wid >> 2) * 64;
    const int wn = (wid & 3) * 32;

    const __nv_bfloat16* Aq = g_quadq_bf + ((size_t)gid * GG + i0) * QKD;
    const __nv_bfloat16* Bk = g_quadk_bf + ((size_t)gid * GG + j0) * QKD;

    auto loadT = [&](const __nv_bfloat16* src, uint32_t base, int s) {
        const __nv_bfloat16* p = src + s * 64;
#pragma unroll
        for (int i = 0; i < 4; i++) {
            int c = tid + i * 256;
            int row = c >> 3, col = c & 7;
            cpa16(base + SW128(row * 128 + col * 16), p + (size_t)row * QKD + col * 8);
        }
    };

    float acc[4][4][4] = {};
    const int a_row = wm + (lane & 15);
    const int a_kof = (lane >> 4) * 8;
    const int b_row = wn + (lane & 7);
    const int b_kof = ((lane >> 3) & 1) * 8;

    loadT(Aq, aB, 0); loadT(Bk, bB, 0); CP_COMMIT();
    for (int s = 0; s < 2; s++) {
        if (s + 1 < 2) {
            loadT(Aq, aB + TILE_B, 1); loadT(Bk, bB + TILE_B, 1);
            CP_COMMIT(); CP_WAIT(1);
        } else CP_WAIT(0);
        __syncthreads();
        const uint32_t abase = aB + s * TILE_B;
        const uint32_t bbase = bB + s * TILE_B;
#pragma unroll
        for (int ks = 0; ks < 4; ks++) {
            uint32_t af[4][4];
#pragma unroll
            for (int mi = 0; mi < 4; mi++)
                ldsm_x4(af[mi], abase + SW128((a_row + mi * 16) * 128 + (ks * 16 + a_kof) * 2));
            uint32_t bf[4][2];
#pragma unroll
            for (int ni = 0; ni < 4; ni++)
                ldsm_x2(bf[ni], bbase + SW128((b_row + ni * 8) * 128 + (ks * 16 + b_kof) * 2));
#pragma unroll
            for (int mi = 0; mi < 4; mi++)
#pragma unroll
                for (int ni = 0; ni < 4; ni++)
                    mma_16816(acc[mi][ni], af[mi], bf[ni]);
        }
        __syncthreads();
    }

    __nv_bfloat16* Cp = g_attn_bf + (size_t)gid * GG * GG;
    const int er = i0 + wm + (lane >> 2);
    const int ec = j0 + wn + (lane & 3) * 2;
#pragma unroll
    for (int mi = 0; mi < 4; mi++)
#pragma unroll
        for (int ni = 0; ni < 4; ni++) {
            int col = ec + ni * 8;
#pragma unroll
            for (int half = 0; half < 2; half++) {
                int row = er + mi * 16 + half * 8;
                float s0 = fmaxf(acc[mi][ni][half * 2 + 0] * (1.0f / GG), 0.0f);
                float s1 = fmaxf(acc[mi][ni][half * 2 + 1] * (1.0f / GG), 0.0f);
                st_bf2(Cp + (size_t)row * GG + col, s0 * s0, s1 * s1);
            }
        }
}

// ====== linkv HMMA: linkv[b,d,e] = sum_n lin_kT[b,d,n] * v[b,n,e] / SEQ ======
__global__ void __launch_bounds__(256)
linkv_hmma_kernel()
{
    constexpr int A_B = 128 * 128;
    constexpr int B_B = 64 * 128;
    extern __shared__ char smem[];
    const uint32_t aB = smem_u32(smem);
    const uint32_t bB = aB + 2 * A_B;

    const int tid = threadIdx.x, wid = tid >> 5, lane = tid & 31;
    const int b  = blockIdx.y;
    const int e0 = blockIdx.x * 64;
    const int wm = (wid & 3) * 32;
    const int wn = (wid >> 2) * 32;

    auto loadA = [&](int s, int buf) {
        uint32_t base = aB + buf * A_B;
        const __nv_bfloat16* src = g_linkT_bf + (size_t)b * QKD * SEQ + s * 64;
#pragma unroll
        for (int i = 0; i < 4; i++) {
            int c = tid + i * 256;
            int row = c >> 3, col = c & 7;
            cpa16(base + SW128(row * 128 + col * 16), src + (size_t)row * SEQ + col * 8);
        }
    };
    auto loadB = [&](int s, int buf) {
        uint32_t base = bB + buf * B_B;
        const __nv_bfloat16* src = g_hq_bf + ((size_t)(b * SEQ + s * 64)) * LDH + e0;
#pragma unroll
        for (int i = 0; i < 2; i++) {
            int c = tid + i * 256;
            int row = c >> 3, col = c & 7;
            cpa16(base + SW128(row * 128 + col * 16), src + (size_t)row * LDH + col * 8);
        }
    };

    float acc[2][4][4] = {};
    const int a_row = wm + (lane & 15);
    const int a_kof = (lane >> 4) * 8;
    const int bt_k  = lane & 15;
    const int bt_n  = ((lane >> 4) & 1) * 8;

    loadA(0, 0); loadB(0, 0); CP_COMMIT();
    for (int s = 0; s < SEQ / 64; s++) {
        if (s + 1 < SEQ / 64) {
            loadA(s + 1, (s + 1) & 1); loadB(s + 1, (s + 1) & 1);
            CP_COMMIT(); CP_WAIT(1);
        } else CP_WAIT(0);
        __syncthreads();
        const uint32_t abase = aB + (s & 1) * A_B;
        const uint32_t bbase = bB + (s & 1) * B_B;
#pragma unroll
        for (int ks = 0; ks < 4; ks++) {
            uint32_t af[2][4];
#pragma unroll
            for (int mi = 0; mi < 2; mi++)
                ldsm_x4(af[mi], abase + SW128((a_row + mi * 16) * 128 + (ks * 16 + a_kof) * 2));
            uint32_t bt[2][4];
#pragma unroll
            for (int g = 0; g < 2; g++)
                ldsm_x4t(bt[g], bbase + SW128((ks * 16 + bt_k) * 128 + (wn + g * 16 + bt_n) * 2));
#pragma unroll
            for (int mi = 0; mi < 2; mi++)
#pragma unroll
                for (int g = 0; g < 2; g++) {
                    mma_16816(acc[mi][g * 2 + 0], af[mi], &bt[g][0]);
                    mma_16816(acc[mi][g * 2 + 1], af[mi], &bt[g][2]);
                }
        }
        __syncthreads();
    }

    __nv_bfloat16* Cp = g_linkv_bf + (size_t)b * QKD * HHID;
    const int er = wm + (lane >> 2);
    const int ec = e0 + wn + (lane & 3) * 2;
#pragma unroll
    for (int mi = 0; mi < 2; mi++)
#pragma unroll
        for (int ni = 0; ni < 4; ni++) {
            int col = ec + ni * 8;
#pragma unroll
            for (int half = 0; half < 2; half++) {
                int row = er + mi * 16 + half * 8;
                st_bf2(Cp + (size_t)row * HHID + col,
                       acc[mi][ni][half * 2 + 0] * (1.0f / SEQ),
                       acc[mi][ni][half * 2 + 1] * (1.0f / SEQ));
            }
        }
}

// ====== fused HMMA: gated = gate * (attn@v + lin_q@lin_kv)  (128p x 128e tile) ======
__global__ void __launch_bounds__(256)
fused_hmma_kernel()
{
    constexpr int TILE_B = 128 * 128;
    extern __shared__ char smem[];
    const uint32_t aB = smem_u32(smem);
    const uint32_t bB = aB + 2 * TILE_B;

    const int tid = threadIdx.x, wid = tid >> 5, lane = tid & 31;
    const int p0 = blockIdx.y * 128, e0 = blockIdx.x * 128;
    const int gid = p0 >> 8, b = p0 >> 11, i0 = p0 & 255;
    const int wm = (wid >> 2) * 64;
    const int wn = (wid & 3) * 32;

    auto loadStage = [&](int s, int buf) {
        uint32_t abase = aB + buf * TILE_B;
        uint32_t bbase = bB + buf * TILE_B;
        if (s < 4) {
            const __nv_bfloat16* asrc = g_attn_bf + (size_t)gid * GG * GG + (size_t)i0 * GG + s * 64;
#pragma unroll
            for (int i = 0; i < 4; i++) {
                int c = tid + i * 256;
                int row = c >> 3, col = c & 7;
                cpa16(abase + SW128(row * 128 + col * 16), asrc + (size_t)row * GG + col * 8);
            }
            const __nv_bfloat16* bsrc = g_hq_bf + ((size_t)(gid * GG + s * 64)) * LDH + e0;
#pragma unroll
            for (int i = 0; i < 4; i++) {
                int c = tid + i * 256;
                int row = c >> 4, col = c & 15;
                cpa16(bbase + SWZ256(row * 256 + col * 16), bsrc + (size_t)row * LDH + col * 8);
            }
        } else {
            int s2 = s - 4;
            const __nv_bfloat16* asrc = g_linq_bf + (size_t)p0 * QKD + s2 * 64;
#pragma unroll
            for (int i = 0; i < 4; i++) {
                int c = tid + i * 256;
                int row = c >> 3, col = c & 7;
                cpa16(abase + SW128(row * 128 + col * 16), asrc + (size_t)row * QKD + col * 8);
            }
            const __nv_bfloat16* bsrc = g_linkv_bf + (size_t)b * QKD * HHID + (size_t)(s2 * 64) * HHID + e0;
#pragma unroll
            for (int i = 0; i < 4; i++) {
                int c = tid + i * 256;
                int row = c >> 4, col = c & 15;
                cpa16(bbase + SWZ256(row * 256 + col * 16), bsrc + (size_t)row * HHID + col * 8);
            }
        }
    };

    float acc[4][4][4] = {};
    const int a_row = wm + (lane & 15);
    const int a_kof = (lane >> 4) * 8;
    const int bt_k  = lane & 15;
    const int bt_n  = ((lane >> 4) & 1) * 8;

    loadStage(0, 0); CP_COMMIT();
    for (int s = 0; s < 6; s++) {
        if (s + 1 < 6) { loadStage(s + 1, (s + 1) & 1); CP_COMMIT(); CP_WAIT(1); }
        else CP_WAIT(0);
        __syncthreads();
        const uint32_t abase = aB + (s & 1) * TILE_B;
        const uint32_t bbase = bB + (s & 1) * TILE_B;
#pragma unroll
        for (int ks = 0; ks < 4; ks++) {
            uint32_t af[4][4];
#pragma unroll
            for (int mi = 0; mi < 4; mi++)
                ldsm_x4(af[mi], abase + SW128((a_row + mi * 16) * 128 + (ks * 16 + a_kof) * 2));
            uint32_t bt[2][4];
#pragma unroll
            for (int g = 0; g < 2; g++)
                ldsm_x4t(bt[g], bbase + SWZ256((ks * 16 + bt_k) * 256 + (wn + g * 16 + bt_n) * 2));
#pragma unroll
            for (int mi = 0; mi < 4; mi++)
#pragma unroll
                for (int g = 0; g < 2; g++) {
                    mma_16816(acc[mi][g * 2 + 0], af[mi], &bt[g][0]);
                    mma_16816(acc[mi][g * 2 + 1], af[mi], &bt[g][2]);
                }
        }
        __syncthreads();
    }

    const int er = p0 + wm + (lane >> 2);
    const int ec = e0 + wn + (lane & 3) * 2;
#pragma unroll
    for (int mi = 0; mi < 4; mi++)
#pragma unroll
        for (int ni = 0; ni < 4; ni++) {
            int col = ec + ni * 8;
#pragma unroll
            for (int half = 0; half < 2; half++) {
                int row = er + mi * 16 + half * 8;
                float g0 = __bfloat162float(g_hq_bf[(size_t)row * LDH + HHID + col + 0]);
                float g1 = __bfloat162float(g_hq_bf[(size_t)row * LDH + HHID + col + 1]);
                st_bf2(g_gated_bf + (size_t)row * HHID + col,
                       g0 * acc[mi][ni][half * 2 + 0], g1 * acc[mi][ni][half * 2 + 1]);
            }
        }
}

// =================== transpose + fp32->bf16 convert ==========
__global__ void transpose_bf_kernel(const float* __restrict__ in,
                                    __nv_bfloat16* __restrict__ out, int R, int Cc) {
    __shared__ float t[32][33];
    int c0 = blockIdx.x * 32, r0 = blockIdx.y * 32;
    int x = threadIdx.x, y = threadIdx.y;
#pragma unroll
    for (int i = 0; i < 32; i += 8)
        t[y + i][x] = in[(size_t)(r0 + y + i) * Cc + c0 + x];
    __syncthreads();
#pragma unroll
    for (int i = 0; i < 32; i += 8)
        out[(size_t)(c0 + y + i) * R + r0 + x] = __float2bfloat16(t[x][y + i]);
}

// -------- prep: concat bias + zero-pad weight rows 4224..4351 --------
__global__ void prep_bias_kernel(const float* __restrict__ bh, const float* __restrict__ bq) {
    int i = blockIdx.x * 256 + threadIdx.x;
    if (i < NCAT)
        g_bcat[i] = (i < QKOFF) ? bh[i] : (i < QKOFF + QKD ? bq[i - QKOFF] : 0.0f);
}
__global__ void prep_pad_kernel() {
    int i = blockIdx.x * 256 + threadIdx.x;   // 128*1024 elements
    g_wcatT[(size_t)(QKOFF + QKD) * DD + i] = __float2bfloat16(0.0f);
}

// ------- RoPE tables: one fp64 pow per BLOCK (thread 0), broadcast via smem -------
__global__ void rope_table_kernel() {
    __shared__ float sf;
    int j = blockIdx.x;
    if (threadIdx.x == 0) sf = (float)pow(10000.0, (double)j / 64.0);
    __syncthreads();
    float invf = sf;
    int n = blockIdx.y * 256 + threadIdx.x;
    float ang = (float)n * invf;
    g_sin[n*64 + j] = sinf(ang);
    g_cos[n*64 + j] = cosf(ang);
}

// ---------------- LayerNorm (emits bf16 A operand) ----------------
__global__ void ln_kernel(const float* __restrict__ x,
                          const float* __restrict__ gam,
                          const float* __restrict__ bet) {
    int row = blockIdx.x, t = threadIdx.x;
    const float* xr = x + (size_t)row * DD;
    float v[4]; float s = 0.f;
#pragma unroll
    for (int c = 0; c < 4; c++) { v[c] = xr[t + 256*c]; s += v[c]; }
    __shared__ float red[8];
    __shared__ float bcast;
    int lane = t & 31, w = t >> 5;
#pragma unroll
    for (int o = 16; o; o >>= 1) s += __shfl_xor_sync(~0u, s, o);
    if (lane == 0) red[w] = s;
    __syncthreads();
    if (t == 0) { float tot = 0; for (int i = 0; i < 8; i++) tot += red[i]; bcast = tot / DD; }
    __syncthreads();
    float mu = bcast;
    float s2 = 0.f;
#pragma unroll
    for (int c = 0; c < 4; c++) { float d = v[c] - mu; s2 += d * d; }
#pragma unroll
    for (int o = 16; o; o >>= 1) s2 += __shfl_xor_sync(~0u, s2, o);
    __syncthreads();
    if (lane == 0) red[w] = s2;
    __syncthreads();
    if (t == 0) { float tot = 0; for (int i = 0; i < 8; i++) tot += red[i];
                  bcast = 1.0f / sqrtf(tot / DD + 1e-5f); }
    __syncthreads();
    float rstd = bcast;
    __nv_bfloat16* out = g_normed_bf + (size_t)row * DD;
#pragma unroll
    for (int c = 0; c < 4; c++) {
        int d = t + 256*c;
        out[d] = __float2bfloat16((v[c] - mu) * rstd * gam[d] + bet[d]);
    }
}

// -------- OffsetScale + RoPE (reads bf16 qk from merged buffer) --------
__global__ void rope_apply_kernel(const float* __restrict__ gamma,
                                  const float* __restrict__ beta) {
    int tid = threadIdx.x;
    int tok = blockIdx.x * 4 + (tid >> 6);
    int j   = tid & 63;
    int n   = tok & (SEQ - 1);
    int b   = tok >> 11;
    float v1 = __bfloat162float(g_hq_bf[(size_t)tok * LDH + QKOFF + j]);
    float v2 = __bfloat162float(g_hq_bf[(size_t)tok * LDH + QKOFF + j + 64]);
    float sn = g_sin[n*64 + j], cs = g_cos[n*64 + j];
    {
        float a1 = v1 * gamma[0*QKD + j]      + beta[0*QKD + j];
        float a2 = v2 * gamma[0*QKD + j + 64] + beta[0*QKD + j + 64];
        g_quadq_bf[(size_t)tok * QKD + j]      = __float2bfloat16(a1 * cs - a2 * sn);
        g_quadq_bf[(size_t)tok * QKD + j + 64] = __float2bfloat16(a2 * cs + a1 * sn);
    }
    {
        float a1 = v1 * gamma[2*QKD + j]      + beta[2*QKD + j];
        float a2 = v2 * gamma[2*QKD + j + 64] + beta[2*QKD + j + 64];
        g_quadk_bf[(size_t)tok * QKD + j]      = __float2bfloat16(a1 * cs - a2 * sn);
        g_quadk_bf[(size_t)tok * QKD + j + 64] = __float2bfloat16(a2 * cs + a1 * sn);
    }
    {
        float a1 = v1 * gamma[1*QKD + j]      + beta[1*QKD + j];
        float a2 = v2 * gamma[1*QKD + j + 64] + beta[1*QKD + j + 64];
        g_linq_bf[(size_t)tok * QKD + j]      = __float2bfloat16(a1 * cs - a2 * sn);
        g_linq_bf[(size_t)tok * QKD + j + 64] = __float2bfloat16(a2 * cs + a1 * sn);
    }
    {
        float a1 = v1 * gamma[3*QKD + j]      + beta[3*QKD + j];
        float a2 = v2 * gamma[3*QKD + j + 64] + beta[3*QKD + j + 64];
        __nv_bfloat16* base = g_linkT_bf + (size_t)b * QKD * SEQ;
        base[(size_t)j * SEQ + n]        = __float2bfloat16(a1 * cs - a2 * sn);
        base[(size_t)(j + 64) * SEQ + n] = __float2bfloat16(a2 * cs + a1 * sn);
    }
}

// ---------------------------------------------------------------------------
extern "C" void kernel_launch(void* const* d_in, const int* in_sizes, int n_in,
                              void* d_out, int out_size) {
    const float* x        = (const float*)d_in[0];
    const float* ln_g     = (const float*)d_in[1];
    const float* ln_b     = (const float*)d_in[2];
    const float* W_hidden = (const float*)d_in[3];
    const float* b_hidden = (const float*)d_in[4];
    const float* W_qk     = (const float*)d_in[5];
    const float* b_qk     = (const float*)d_in[6];
    const float* os_gamma = (const float*)d_in[7];
    const float* os_beta  = (const float*)d_in[8];
    const float* W_out    = (const float*)d_in[9];
    const float* b_out    = (const float*)d_in[10];
    float* out = (float*)d_out;

    __nv_bfloat16 *normed_bf, *wcatT, *woT, *gated_bf, *hq_bf;
    float *bcat;
    cudaGetSymbolAddress((void**)&normed_bf, g_normed_bf);
    cudaGetSymbolAddress((void**)&wcatT, g_wcatT);
    cudaGetSymbolAddress((void**)&woT,   g_woT);
    cudaGetSymbolAddress((void**)&gated_bf, g_gated_bf);
    cudaGetSymbolAddress((void**)&hq_bf, g_hq_bf);
    cudaGetSymbolAddress((void**)&bcat,  g_bcat);

    const int SMEM_BIG  = 4 * (16384 + 32768);   // 196608
    const int SMEM_ATTN = 4 * 128 * 128;         // 64 KB
    const int SMEM_LK   = 2 * 16384 + 2 * 8192;  // 48 KB
    cudaFuncSetAttribute(mm_bf16_kernel<1024,true,false,true>,
                         cudaFuncAttributeMaxDynamicSharedMemorySize, SMEM_BIG);
    cudaFuncSetAttribute(mm_bf16_kernel<2048,false,true,false>,
                         cudaFuncAttributeMaxDynamicSharedMemorySize, SMEM_BIG);
    cudaFuncSetAttribute(attn_hmma_kernel,
                         cudaFuncAttributeMaxDynamicSharedMemorySize, SMEM_ATTN);
    cudaFuncSetAttribute(linkv_hmma_kernel,
                         cudaFuncAttributeMaxDynamicSharedMemorySize, SMEM_LK);
    cudaFuncSetAttribute(fused_hmma_kernel,
                         cudaFuncAttributeMaxDynamicSharedMemorySize, SMEM_ATTN);

    // combined weight: [W_hidden | W_qk]^T rows 0..4223, zero-pad 4224..4351
    transpose_bf_kernel<<<dim3(TWOH/32, DD/32), dim3(32,8)>>>(W_hidden, wcatT, DD, TWOH);
    transpose_bf_kernel<<<dim3(QKD/32,  DD/32), dim3(32,8)>>>(W_qk, wcatT + (size_t)QKOFF*DD, DD, QKD);
    prep_pad_kernel<<<(QKD*DD)/256, 256>>>();
    prep_bias_kernel<<<(NCAT+255)/256, 256>>>(b_hidden, b_qk);
    transpose_bf_kernel<<<dim3(DD/32, HHID/32), dim3(32,8)>>>(W_out, woT, HHID, DD);

    rope_table_kernel<<<dim3(64, SEQ/256), 256>>>();
    ln_kernel<<<MROWS, 256>>>(x, ln_g, ln_b);

    // [h | qk] = silu(normed @ Wcat + bcat) -> bf16 [8192, 4352]
    mm_bf16_kernel<1024,true,false,true><<<dim3(NCAT/256, MROWS/128), 256, SMEM_BIG>>>(
        normed_bf, wcatT, bcat, nullptr, nullptr, hq_bf, LDH);

    rope_apply_kernel<<<MROWS/4, 256>>>(os_gamma, os_beta);
    attn_hmma_kernel<<<dim3(GG/128, GG/128, NGRP), 256, SMEM_ATTN>>>();
    linkv_hmma_kernel<<<dim3(HHID/64, BB), 256, SMEM_LK>>>();
    fused_hmma_kernel<<<dim3(HHID/128, MROWS/128), 256, SMEM_ATTN>>>();

    // out = gated @ W_out + b_out + x  [8192, 1024]
    mm_bf16_kernel<2048,false,true,false><<<dim3(DD/256, MROWS/128), 256, SMEM_BIG>>>(
        gated_bf, woT, b_out, x, out, nullptr, DD);
}

// round 15
// speedup vs baseline: 1.0573x; 1.0573x over previous
#include <cuda_runtime.h>
#include <cuda_bf16.h>
#include <math.h>
#include <cstdint>

// Problem constants
#define BB   4
#define SEQ  2048
#define DD   1024
#define GG   256
#define QKD  128
#define HHID 2048
#define MROWS (BB*SEQ)        // 8192
#define NGRP  (MROWS/GG)      // 32
#define TWOH  (2*HHID)        // 4096

// -------- device scratch (no cudaMalloc allowed) --------
__device__ __nv_bfloat16 g_normed_bf[(size_t)MROWS*DD];    // 16 MB
__device__ __nv_bfloat16 g_h_bf[(size_t)MROWS*TWOH];       // 64 MB (v | gate)
__device__ float g_qk[(size_t)MROWS*QKD];                  // 4 MB
__device__ __nv_bfloat16 g_quadq_bf[(size_t)MROWS*QKD];    // 2 MB
__device__ __nv_bfloat16 g_quadk_bf[(size_t)MROWS*QKD];    // 2 MB
__device__ __nv_bfloat16 g_linq_bf[(size_t)MROWS*QKD];     // 2 MB
__device__ __nv_bfloat16 g_linkT_bf[(size_t)BB*QKD*SEQ];   // 2 MB  lin_k^T [b][d][n]
__device__ __nv_bfloat16 g_attn_bf[(size_t)NGRP*GG*GG];    // 4 MB
__device__ __nv_bfloat16 g_linkv_bf[(size_t)BB*QKD*HHID];  // 2 MB
__device__ __nv_bfloat16 g_gated_bf[(size_t)MROWS*HHID];   // 32 MB
__device__ __nv_bfloat16 g_whT[(size_t)TWOH*DD];           // 8 MB
__device__ __nv_bfloat16 g_wqkT[(size_t)QKD*DD];           // 0.25 MB
__device__ __nv_bfloat16 g_woT[(size_t)DD*HHID];           // 4 MB
__device__ float g_sin[SEQ*64];
__device__ float g_cos[SEQ*64];

// =================== PTX helpers (arch-portable: sm_80+ subset) ===================
__device__ __forceinline__ uint32_t smem_u32(const void* p) {
    uint32_t a;
    asm("{ .reg .u64 t; cvta.to.shared.u64 t, %1; cvt.u32.u64 %0, t; }" : "=r"(a) : "l"(p));
    return a;
}
#define SW128(o) ((o) ^ (((o) >> 3) & 0x70))   // 128B rows
#define SWZ256(o) ((o) ^ (((o) >> 4) & 0x70))  // 256B rows

__device__ __forceinline__ void cpa16(uint32_t dst, const void* src) {
    asm volatile("cp.async.cg.shared.global [%0], [%1], 16;" :: "r"(dst), "l"(src));
}
#define CP_COMMIT() asm volatile("cp.async.commit_group;" ::: "memory")
#define CP_WAIT(n)  asm volatile("cp.async.wait_group %0;" :: "n"(n) : "memory")

__device__ __forceinline__ void ldsm_x4(uint32_t* r, uint32_t addr) {
    asm volatile("ldmatrix.sync.aligned.m8n8.x4.shared.b16 {%0,%1,%2,%3}, [%4];"
                 : "=r"(r[0]), "=r"(r[1]), "=r"(r[2]), "=r"(r[3]) : "r"(addr));
}
__device__ __forceinline__ void ldsm_x2(uint32_t* r, uint32_t addr) {
    asm volatile("ldmatrix.sync.aligned.m8n8.x2.shared.b16 {%0,%1}, [%2];"
                 : "=r"(r[0]), "=r"(r[1]) : "r"(addr));
}
__device__ __forceinline__ void ldsm_x4t(uint32_t* r, uint32_t addr) {
    asm volatile("ldmatrix.sync.aligned.m8n8.x4.trans.shared.b16 {%0,%1,%2,%3}, [%4];"
                 : "=r"(r[0]), "=r"(r[1]), "=r"(r[2]), "=r"(r[3]) : "r"(addr));
}
__device__ __forceinline__ void mma_16816(float* c, const uint32_t* a, const uint32_t* b) {
    asm volatile(
        "mma.sync.aligned.m16n8k16.row.col.f32.bf16.bf16.f32 "
        "{%0,%1,%2,%3}, {%4,%5,%6,%7}, {%8,%9}, {%0,%1,%2,%3};"
        : "+f"(c[0]), "+f"(c[1]), "+f"(c[2]), "+f"(c[3])
        : "r"(a[0]), "r"(a[1]), "r"(a[2]), "r"(a[3]), "r"(b[0]), "r"(b[1]));
}
__device__ __forceinline__ void st_bf2(__nv_bfloat16* p, float a, float b) {
    *(__nv_bfloat162*)p = __floats2bfloat162_rn(a, b);
}

// ====== bf16 tensor-core GEMM: C[M,N] = A[M,K] @ Bt[N,K]^T ======
// CTA tile 128 x N_CTA, 8 warps (2x4), warp tile 64 x (N_CTA/4).
// 4-stage cp.async ring, two barriers/stage (R11-validated), B frags via ldmatrix.x4.
template<int N_CTA, int K_TOT, bool SILU_, bool RESID_, bool OUTBF_>
__global__ void __launch_bounds__(256, 1)
mm_bf16_kernel(const __nv_bfloat16* __restrict__ A,
               const __nv_bfloat16* __restrict__ Bt,
               const float* __restrict__ bias,
               const float* __restrict__ resid,
               float* __restrict__ Cf, __nv_bfloat16* __restrict__ Cb, int ldC)
{
    constexpr int STAGES = K_TOT / 64;
    constexpr int A_B    = 128 * 128;       // 16 KB
    constexpr int B_B    = N_CTA * 128;     // 16/32 KB
    constexpr int NI     = N_CTA / 32;      // mma n8-tiles per warp (4 or 8)
    constexpr int NQ     = NI / 2;          // 16-wide n blocks per warp (2 or 4)
    constexpr int NBCH   = N_CTA / 32;
    extern __shared__ char smem[];
    const uint32_t aB = smem_u32(smem);
    const uint32_t bB = aB + 4 * A_B;

    const int tid = threadIdx.x, wid = tid >> 5, lane = tid & 31;
    const int m0 = blockIdx.y * 128, n0 = blockIdx.x * N_CTA;
    const int wm = (wid >> 2) * 64;
    const int wn = (wid & 3) * (N_CTA / 4);

    auto loadA = [&](int s, int buf) {
        uint32_t base = aB + buf * A_B;
        const __nv_bfloat16* src = A + (size_t)m0 * K_TOT + s * 64;
#pragma unroll
        for (int i = 0; i < 4; i++) {
            int c = tid + i * 256;
            int row = c >> 3, col = c & 7;
            cpa16(base + SW128(row * 128 + col * 16), src + (size_t)row * K_TOT + col * 8);
        }
    };
    auto loadB = [&](int s, int buf) {
        uint32_t base = bB + buf * B_B;
        const __nv_bfloat16* src = Bt + (size_t)n0 * K_TOT + s * 64;
#pragma unroll
        for (int i = 0; i < NBCH; i++) {
            int c = tid + i * 256;
            int row = c >> 3, col = c & 7;
            cpa16(base + SW128(row * 128 + col * 16), src + (size_t)row * K_TOT + col * 8);
        }
    };

    float acc[4][NI][4] = {};
    const int a_row = wm + (lane & 15);
    const int a_kof = (lane >> 4) * 8;
    // B via x4: lane-group g = lane>>3 maps to (n-half, k-half) of a 16x16 block:
    //   g0=(n0,k0), g1=(n0,k1), g2=(n1,k0), g3=(n1,k1)  ->  regs {n0k0,n0k1,n1k0,n1k1}
    const int bq_ro = (lane >> 4) * 8 + (lane & 7);
    const int bq_ko = ((lane >> 3) & 1) * 8;

    loadA(0, 0); loadB(0, 0); CP_COMMIT();
    loadA(1, 1); loadB(1, 1); CP_COMMIT();
    loadA(2, 2); loadB(2, 2); CP_COMMIT();

    for (int s = 0; s < STAGES; s++) {
        if (s + 3 < STAGES) {
            loadA(s + 3, (s + 3) & 3); loadB(s + 3, (s + 3) & 3);
            CP_COMMIT(); CP_WAIT(3);
        } else if (s + 2 < STAGES) CP_WAIT(2);
        else if (s + 1 < STAGES) CP_WAIT(1);
        else CP_WAIT(0);
        __syncthreads();
        const uint32_t abase = aB + (s & 3) * A_B;
        const uint32_t bbase = bB + (s & 3) * B_B;
#pragma unroll
        for (int ks = 0; ks < 4; ks++) {
            uint32_t af[4][4];
#pragma unroll
            for (int mi = 0; mi < 4; mi++)
                ldsm_x4(af[mi], abase + SW128((a_row + mi * 16) * 128 + (ks * 16 + a_kof) * 2));
            uint32_t bq[NQ][4];
#pragma unroll
            for (int nn = 0; nn < NQ; nn++) {
                int row = wn + nn * 16 + bq_ro;
                ldsm_x4(bq[nn], bbase + SW128(row * 128 + (ks * 16 + bq_ko) * 2));
            }
#pragma unroll
            for (int mi = 0; mi < 4; mi++)
#pragma unroll
                for (int nn = 0; nn < NQ; nn++) {
                    mma_16816(acc[mi][2 * nn + 0], af[mi], &bq[nn][0]);
                    mma_16816(acc[mi][2 * nn + 1], af[mi], &bq[nn][2]);
                }
        }
        __syncthreads();
    }

    const int er = m0 + wm + (lane >> 2);
    const int ec = n0 + wn + (lane & 3) * 2;
#pragma unroll
    for (int mi = 0; mi < 4; mi++)
#pragma unroll
        for (int ni = 0; ni < NI; ni++) {
            int col = ec + ni * 8;
#pragma unroll
            for (int half = 0; half < 2; half++) {
                int row = er + mi * 16 + half * 8;
                float v0 = acc[mi][ni][half * 2 + 0] + bias[col + 0];
                float v1 = acc[mi][ni][half * 2 + 1] + bias[col + 1];
                if (SILU_) { v0 = v0 / (1.0f + expf(-v0)); v1 = v1 / (1.0f + expf(-v1)); }
                if (RESID_) {
                    v0 += resid[(size_t)row * ldC + col + 0];
                    v1 += resid[(size_t)row * ldC + col + 1];
                }
                if (OUTBF_) st_bf2(Cb + (size_t)row * ldC + col, v0, v1);
                else { float2 o; o.x = v0; o.y = v1; *(float2*)(Cf + (size_t)row * ldC + col) = o; }
            }
        }
}

// ====== attn HMMA: attn = relu(quad_q @ quad_k^T / g)^2 -> bf16  (128x128 tile) ======
__global__ void __launch_bounds__(256)
attn_hmma_kernel()
{
    constexpr int TILE_B = 128 * 128;
    extern __shared__ char smem[];
    const uint32_t aB = smem_u32(smem);
    const uint32_t bB = aB + 2 * TILE_B;

    const int tid = threadIdx.x, wid = tid >> 5, lane = tid & 31;
    const int gid = blockIdx.z;
    const int i0 = blockIdx.y * 128, j0 = blockIdx.x * 128;
    const int wm = (wid >> 2) * 64;
    const int wn = (wid & 3) * 32;

    const __nv_bfloat16* Aq = g_quadq_bf + ((size_t)gid * GG + i0) * QKD;
    const __nv_bfloat16* Bk = g_quadk_bf + ((size_t)gid * GG + j0) * QKD;

    auto loadT = [&](const __nv_bfloat16* src, uint32_t base, int s) {
        const __nv_bfloat16* p = src + s * 64;
#pragma unroll
        for (int i = 0; i < 4; i++) {
            int c = tid + i * 256;
            int row = c >> 3, col = c & 7;
            cpa16(base + SW128(row * 128 + col * 16), p + (size_t)row * QKD + col * 8);
        }
    };

    float acc[4][4][4] = {};
    const int a_row = wm + (lane & 15);
    const int a_kof = (lane >> 4) * 8;
    const int b_row = wn + (lane & 7);
    const int b_kof = ((lane >> 3) & 1) * 8;

    loadT(Aq, aB, 0); loadT(Bk, bB, 0); CP_COMMIT();
    for (int s = 0; s < 2; s++) {
        if (s + 1 < 2) {
            loadT(Aq, aB + TILE_B, 1); loadT(Bk, bB + TILE_B, 1);
            CP_COMMIT(); CP_WAIT(1);
        } else CP_WAIT(0);
        __syncthreads();
        const uint32_t abase = aB + s * TILE_B;
        const uint32_t bbase = bB + s * TILE_B;
#pragma unroll
        for (int ks = 0; ks < 4; ks++) {
            uint32_t af[4][4];
#pragma unroll
            for (int mi = 0; mi < 4; mi++)
                ldsm_x4(af[mi], abase + SW128((a_row + mi * 16) * 128 + (ks * 16 + a_kof) * 2));
            uint32_t bf[4][2];
#pragma unroll
            for (int ni = 0; ni < 4; ni++)
                ldsm_x2(bf[ni], bbase + SW128((b_row + ni * 8) * 128 + (ks * 16 + b_kof) * 2));
#pragma unroll
            for (int mi = 0; mi < 4; mi++)
#pragma unroll
                for (int ni = 0; ni < 4; ni++)
                    mma_16816(acc[mi][ni], af[mi], bf[ni]);
        }
        __syncthreads();
    }

    __nv_bfloat16* Cp = g_attn_bf + (size_t)gid * GG * GG;
    const int er = i0 + wm + (lane >> 2);
    const int ec = j0 + wn + (lane & 3) * 2;
#pragma unroll
    for (int mi = 0; mi < 4; mi++)
#pragma unroll
        for (int ni = 0; ni < 4; ni++) {
            int col = ec + ni * 8;
#pragma unroll
            for (int half = 0; half < 2; half++) {
                int row = er + mi * 16 + half * 8;
                float s0 = fmaxf(acc[mi][ni][half * 2 + 0] * (1.0f / GG), 0.0f);
                float s1 = fmaxf(acc[mi][ni][half * 2 + 1] * (1.0f / GG), 0.0f);
                st_bf2(Cp + (size_t)row * GG + col, s0 * s0, s1 * s1);
            }
        }
}

// ====== linkv HMMA: linkv[b,d,e] = sum_n lin_kT[b,d,n] * v[b,n,e] / SEQ ======
__global__ void __launch_bounds__(256)
linkv_hmma_kernel()
{
    constexpr int A_B = 128 * 128;
    constexpr int B_B = 64 * 128;
    extern __shared__ char smem[];
    const uint32_t aB = smem_u32(smem);
    const uint32_t bB = aB + 2 * A_B;

    const int tid = threadIdx.x, wid = tid >> 5, lane = tid & 31;
    const int b  = blockIdx.y;
    const int e0 = blockIdx.x * 64;
    const int wm = (wid & 3) * 32;
    const int wn = (wid >> 2) * 32;

    auto loadA = [&](int s, int buf) {
        uint32_t base = aB + buf * A_B;
        const __nv_bfloat16* src = g_linkT_bf + (size_t)b * QKD * SEQ + s * 64;
#pragma unroll
        for (int i = 0; i < 4; i++) {
            int c = tid + i * 256;
            int row = c >> 3, col = c & 7;
            cpa16(base + SW128(row * 128 + col * 16), src + (size_t)row * SEQ + col * 8);
        }
    };
    auto loadB = [&](int s, int buf) {
        uint32_t base = bB + buf * B_B;
        const __nv_bfloat16* src = g_h_bf + ((size_t)(b * SEQ + s * 64)) * TWOH + e0;
#pragma unroll
        for (int i = 0; i < 2; i++) {
            int c = tid + i * 256;
            int row = c >> 3, col = c & 7;
            cpa16(base + SW128(row * 128 + col * 16), src + (size_t)row * TWOH + col * 8);
        }
    };

    float acc[2][4][4] = {};
    const int a_row = wm + (lane & 15);
    const int a_kof = (lane >> 4) * 8;
    const int bt_k  = lane & 15;
    const int bt_n  = ((lane >> 4) & 1) * 8;

    loadA(0, 0); loadB(0, 0); CP_COMMIT();
    for (int s = 0; s < SEQ / 64; s++) {
        if (s + 1 < SEQ / 64) {
            loadA(s + 1, (s + 1) & 1); loadB(s + 1, (s + 1) & 1);
            CP_COMMIT(); CP_WAIT(1);
        } else CP_WAIT(0);
        __syncthreads();
        const uint32_t abase = aB + (s & 1) * A_B;
        const uint32_t bbase = bB + (s & 1) * B_B;
#pragma unroll
        for (int ks = 0; ks < 4; ks++) {
            uint32_t af[2][4];
#pragma unroll
            for (int mi = 0; mi < 2; mi++)
                ldsm_x4(af[mi], abase + SW128((a_row + mi * 16) * 128 + (ks * 16 + a_kof) * 2));
            uint32_t bt[2][4];
#pragma unroll
            for (int g = 0; g < 2; g++)
                ldsm_x4t(bt[g], bbase + SW128((ks * 16 + bt_k) * 128 + (wn + g * 16 + bt_n) * 2));
#pragma unroll
            for (int mi = 0; mi < 2; mi++)
#pragma unroll
                for (int g = 0; g < 2; g++) {
                    mma_16816(acc[mi][g * 2 + 0], af[mi], &bt[g][0]);
                    mma_16816(acc[mi][g * 2 + 1], af[mi], &bt[g][2]);
                }
        }
        __syncthreads();
    }

    __nv_bfloat16* Cp = g_linkv_bf + (size_t)b * QKD * HHID;
    const int er = wm + (lane >> 2);
    const int ec = e0 + wn + (lane & 3) * 2;
#pragma unroll
    for (int mi = 0; mi < 2; mi++)
#pragma unroll
        for (int ni = 0; ni < 4; ni++) {
            int col = ec + ni * 8;
#pragma unroll
            for (int half = 0; half < 2; half++) {
                int row = er + mi * 16 + half * 8;
                st_bf2(Cp + (size_t)row * HHID + col,
                       acc[mi][ni][half * 2 + 0] * (1.0f / SEQ),
                       acc[mi][ni][half * 2 + 1] * (1.0f / SEQ));
            }
        }
}

// ====== fused HMMA: gated = gate * (attn@v + lin_q@lin_kv)  (128p x 128e tile) ======
__global__ void __launch_bounds__(256)
fused_hmma_kernel()
{
    constexpr int TILE_B = 128 * 128;
    extern __shared__ char smem[];
    const uint32_t aB = smem_u32(smem);
    const uint32_t bB = aB + 2 * TILE_B;

    const int tid = threadIdx.x, wid = tid >> 5, lane = tid & 31;
    const int p0 = blockIdx.y * 128, e0 = blockIdx.x * 128;
    const int gid = p0 >> 8, b = p0 >> 11, i0 = p0 & 255;
    const int wm = (wid >> 2) * 64;
    const int wn = (wid & 3) * 32;

    auto loadStage = [&](int s, int buf) {
        uint32_t abase = aB + buf * TILE_B;
        uint32_t bbase = bB + buf * TILE_B;
        if (s < 4) {
            const __nv_bfloat16* asrc = g_attn_bf + (size_t)gid * GG * GG + (size_t)i0 * GG + s * 64;
#pragma unroll
            for (int i = 0; i < 4; i++) {
                int c = tid + i * 256;
                int row = c >> 3, col = c & 7;
                cpa16(abase + SW128(row * 128 + col * 16), asrc + (size_t)row * GG + col * 8);
            }
            const __nv_bfloat16* bsrc = g_h_bf + ((size_t)(gid * GG + s * 64)) * TWOH + e0;
#pragma unroll
            for (int i = 0; i < 4; i++) {
                int c = tid + i * 256;
                int row = c >> 4, col = c & 15;
                cpa16(bbase + SWZ256(row * 256 + col * 16), bsrc + (size_t)row * TWOH + col * 8);
            }
        } else {
            int s2 = s - 4;
            const __nv_bfloat16* asrc = g_linq_bf + (size_t)p0 * QKD + s2 * 64;
#pragma unroll
            for (int i = 0; i < 4; i++) {
                int c = tid + i * 256;
                int row = c >> 3, col = c & 7;
                cpa16(abase + SW128(row * 128 + col * 16), asrc + (size_t)row * QKD + col * 8);
            }
            const __nv_bfloat16* bsrc = g_linkv_bf + (size_t)b * QKD * HHID + (size_t)(s2 * 64) * HHID + e0;
#pragma unroll
            for (int i = 0; i < 4; i++) {
                int c = tid + i * 256;
                int row = c >> 4, col = c & 15;
                cpa16(bbase + SWZ256(row * 256 + col * 16), bsrc + (size_t)row * HHID + col * 8);
            }
        }
    };

    float acc[4][4][4] = {};
    const int a_row = wm + (lane & 15);
    const int a_kof = (lane >> 4) * 8;
    const int bt_k  = lane & 15;
    const int bt_n  = ((lane >> 4) & 1) * 8;

    loadStage(0, 0); CP_COMMIT();
    for (int s = 0; s < 6; s++) {
        if (s + 1 < 6) { loadStage(s + 1, (s + 1) & 1); CP_COMMIT(); CP_WAIT(1); }
        else CP_WAIT(0);
        __syncthreads();
        const uint32_t abase = aB + (s & 1) * TILE_B;
        const uint32_t bbase = bB + (s & 1) * TILE_B;
#pragma unroll
        for (int ks = 0; ks < 4; ks++) {
            uint32_t af[4][4];
#pragma unroll
            for (int mi = 0; mi < 4; mi++)
                ldsm_x4(af[mi], abase + SW128((a_row + mi * 16) * 128 + (ks * 16 + a_kof) * 2));
            uint32_t bt[2][4];
#pragma unroll
            for (int g = 0; g < 2; g++)
                ldsm_x4t(bt[g], bbase + SWZ256((ks * 16 + bt_k) * 256 + (wn + g * 16 + bt_n) * 2));
#pragma unroll
            for (int mi = 0; mi < 4; mi++)
#pragma unroll
                for (int g = 0; g < 2; g++) {
                    mma_16816(acc[mi][g * 2 + 0], af[mi], &bt[g][0]);
                    mma_16816(acc[mi][g * 2 + 1], af[mi], &bt[g][2]);
                }
        }
        __syncthreads();
    }

    const int er = p0 + wm + (lane >> 2);
    const int ec = e0 + wn + (lane & 3) * 2;
#pragma unroll
    for (int mi = 0; mi < 4; mi++)
#pragma unroll
        for (int ni = 0; ni < 4; ni++) {
            int col = ec + ni * 8;
#pragma unroll
            for (int half = 0; half < 2; half++) {
                int row = er + mi * 16 + half * 8;
                float g0 = __bfloat162float(g_h_bf[(size_t)row * TWOH + HHID + col + 0]);
                float g1 = __bfloat162float(g_h_bf[(size_t)row * TWOH + HHID + col + 1]);
                st_bf2(g_gated_bf + (size_t)row * HHID + col,
                       g0 * acc[mi][ni][half * 2 + 0], g1 * acc[mi][ni][half * 2 + 1]);
            }
        }
}

// =================== transpose + fp32->bf16 convert ==========
__global__ void transpose_bf_kernel(const float* __restrict__ in,
                                    __nv_bfloat16* __restrict__ out, int R, int Cc) {
    __shared__ float t[32][33];
    int c0 = blockIdx.x * 32, r0 = blockIdx.y * 32;
    int x = threadIdx.x, y = threadIdx.y;
#pragma unroll
    for (int i = 0; i < 32; i += 8)
        t[y + i][x] = in[(size_t)(r0 + y + i) * Cc + c0 + x];
    __syncthreads();
#pragma unroll
    for (int i = 0; i < 32; i += 8)
        out[(size_t)(c0 + y + i) * R + r0 + x] = __float2bfloat16(t[x][y + i]);
}

// ------- RoPE tables: one fp64 pow per BLOCK (thread 0), broadcast via smem -------
__global__ void rope_table_kernel() {
    __shared__ float sf;
    int j = blockIdx.x;
    if (threadIdx.x == 0) sf = (float)pow(10000.0, (double)j / 64.0);
    __syncthreads();
    float invf = sf;
    int n = blockIdx.y * 256 + threadIdx.x;
    float ang = (float)n * invf;
    g_sin[n*64 + j] = sinf(ang);
    g_cos[n*64 + j] = cosf(ang);
}

// ---------------- LayerNorm (emits bf16 A operand) ----------------
__global__ void ln_kernel(const float* __restrict__ x,
                          const float* __restrict__ gam,
                          const float* __restrict__ bet) {
    int row = blockIdx.x, t = threadIdx.x;
    const float* xr = x + (size_t)row * DD;
    float v[4]; float s = 0.f;
#pragma unroll
    for (int c = 0; c < 4; c++) { v[c] = xr[t + 256*c]; s += v[c]; }
    __shared__ float red[8];
    __shared__ float bcast;
    int lane = t & 31, w = t >> 5;
#pragma unroll
    for (int o = 16; o; o >>= 1) s += __shfl_xor_sync(~0u, s, o);
    if (lane == 0) red[w] = s;
    __syncthreads();
    if (t == 0) { float tot = 0; for (int i = 0; i < 8; i++) tot += red[i]; bcast = tot / DD; }
    __syncthreads();
    float mu = bcast;
    float s2 = 0.f;
#pragma unroll
    for (int c = 0; c < 4; c++) { float d = v[c] - mu; s2 += d * d; }
#pragma unroll
    for (int o = 16; o; o >>= 1) s2 += __shfl_xor_sync(~0u, s2, o);
    __syncthreads();
    if (lane == 0) red[w] = s2;
    __syncthreads();
    if (t == 0) { float tot = 0; for (int i = 0; i < 8; i++) tot += red[i];
                  bcast = 1.0f / sqrtf(tot / DD + 1e-5f); }
    __syncthreads();
    float rstd = bcast;
    __nv_bfloat16* out = g_normed_bf + (size_t)row * DD;
#pragma unroll
    for (int c = 0; c < 4; c++) {
        int d = t + 256*c;
        out[d] = __float2bfloat16((v[c] - mu) * rstd * gam[d] + bet[d]);
    }
}

// -------- OffsetScale + RoPE: all four heads -> bf16 --------
__global__ void rope_apply_kernel(const float* __restrict__ gamma,
                                  const float* __restrict__ beta) {
    int tid = threadIdx.x;
    int tok = blockIdx.x * 4 + (tid >> 6);
    int j   = tid & 63;
    int n   = tok & (SEQ - 1);
    int b   = tok >> 11;
    float v1 = g_qk[(size_t)tok * QKD + j];
    float v2 = g_qk[(size_t)tok * QKD + j + 64];
    float sn = g_sin[n*64 + j], cs = g_cos[n*64 + j];
    {
        float a1 = v1 * gamma[0*QKD + j]      + beta[0*QKD + j];
        float a2 = v2 * gamma[0*QKD + j + 64] + beta[0*QKD + j + 64];
        g_quadq_bf[(size_t)tok * QKD + j]      = __float2bfloat16(a1 * cs - a2 * sn);
        g_quadq_bf[(size_t)tok * QKD + j + 64] = __float2bfloat16(a2 * cs + a1 * sn);
    }
    {
        float a1 = v1 * gamma[2*QKD + j]      + beta[2*QKD + j];
        float a2 = v2 * gamma[2*QKD + j + 64] + beta[2*QKD + j + 64];
        g_quadk_bf[(size_t)tok * QKD + j]      = __float2bfloat16(a1 * cs - a2 * sn);
        g_quadk_bf[(size_t)tok * QKD + j + 64] = __float2bfloat16(a2 * cs + a1 * sn);
    }
    {
        float a1 = v1 * gamma[1*QKD + j]      + beta[1*QKD + j];
        float a2 = v2 * gamma[1*QKD + j + 64] + beta[1*QKD + j + 64];
        g_linq_bf[(size_t)tok * QKD + j]      = __float2bfloat16(a1 * cs - a2 * sn);
        g_linq_bf[(size_t)tok * QKD + j + 64] = __float2bfloat16(a2 * cs + a1 * sn);
    }
    {
        float a1 = v1 * gamma[3*QKD + j]      + beta[3*QKD + j];
        float a2 = v2 * gamma[3*QKD + j + 64] + beta[3*QKD + j + 64];
        __nv_bfloat16* base = g_linkT_bf + (size_t)b * QKD * SEQ;
        base[(size_t)j * SEQ + n]        = __float2bfloat16(a1 * cs - a2 * sn);
        base[(size_t)(j + 64) * SEQ + n] = __float2bfloat16(a2 * cs + a1 * sn);
    }
}

// ---------------------------------------------------------------------------
extern "C" void kernel_launch(void* const* d_in, const int* in_sizes, int n_in,
                              void* d_out, int out_size) {
    const float* x        = (const float*)d_in[0];
    const float* ln_g     = (const float*)d_in[1];
    const float* ln_b     = (const float*)d_in[2];
    const float* W_hidden = (const float*)d_in[3];
    const float* b_hidden = (const float*)d_in[4];
    const float* W_qk     = (const float*)d_in[5];
    const float* b_qk     = (const float*)d_in[6];
    const float* os_gamma = (const float*)d_in[7];
    const float* os_beta  = (const float*)d_in[8];
    const float* W_out    = (const float*)d_in[9];
    const float* b_out    = (const float*)d_in[10];
    float* out = (float*)d_out;

    __nv_bfloat16 *normed_bf, *whT, *wqkT, *woT, *gated_bf, *h_bf;
    float *qk;
    cudaGetSymbolAddress((void**)&normed_bf, g_normed_bf);
    cudaGetSymbolAddress((void**)&whT,  g_whT);
    cudaGetSymbolAddress((void**)&wqkT, g_wqkT);
    cudaGetSymbolAddress((void**)&woT,  g_woT);
    cudaGetSymbolAddress((void**)&gated_bf, g_gated_bf);
    cudaGetSymbolAddress((void**)&h_bf, g_h_bf);
    cudaGetSymbolAddress((void**)&qk, g_qk);

    const int SMEM_BIG   = 4 * (16384 + 32768);   // 196608 (N_CTA=256)
    const int SMEM_SMALL = 4 * (16384 + 16384);   // 131072 (N_CTA=128)
    const int SMEM_ATTN  = 4 * 128 * 128;         // 64 KB
    const int SMEM_LK    = 2 * 16384 + 2 * 8192;  // 48 KB
    cudaFuncSetAttribute(mm_bf16_kernel<256,1024,true,false,true>,
                         cudaFuncAttributeMaxDynamicSharedMemorySize, SMEM_BIG);
    cudaFuncSetAttribute(mm_bf16_kernel<128,1024,true,false,false>,
                         cudaFuncAttributeMaxDynamicSharedMemorySize, SMEM_SMALL);
    cudaFuncSetAttribute(mm_bf16_kernel<256,2048,false,true,false>,
                         cudaFuncAttributeMaxDynamicSharedMemorySize, SMEM_BIG);
    cudaFuncSetAttribute(attn_hmma_kernel,
                         cudaFuncAttributeMaxDynamicSharedMemorySize, SMEM_ATTN);
    cudaFuncSetAttribute(linkv_hmma_kernel,
                         cudaFuncAttributeMaxDynamicSharedMemorySize, SMEM_LK);
    cudaFuncSetAttribute(fused_hmma_kernel,
                         cudaFuncAttributeMaxDynamicSharedMemorySize, SMEM_ATTN);

    transpose_bf_kernel<<<dim3(TWOH/32, DD/32), dim3(32,8)>>>(W_hidden, whT, DD, TWOH);
    transpose_bf_kernel<<<dim3(QKD/32,  DD/32), dim3(32,8)>>>(W_qk,  wqkT, DD, QKD);
    transpose_bf_kernel<<<dim3(DD/32, HHID/32), dim3(32,8)>>>(W_out, woT,  HHID, DD);

    rope_table_kernel<<<dim3(64, SEQ/256), 256>>>();
    ln_kernel<<<MROWS, 256>>>(x, ln_g, ln_b);

    // h = silu(normed @ W_hidden + b) -> bf16 [8192, 4096]
    mm_bf16_kernel<256,1024,true,false,true><<<dim3(TWOH/256, MROWS/128), 256, SMEM_BIG>>>(
        normed_bf, whT, b_hidden, nullptr, nullptr, h_bf, TWOH);
    // qk = silu(normed @ W_qk + b) -> fp32 [8192, 128]
    mm_bf16_kernel<128,1024,true,false,false><<<dim3(QKD/128, MROWS/128), 256, SMEM_SMALL>>>(
        normed_bf, wqkT, b_qk, nullptr, qk, nullptr, QKD);

    rope_apply_kernel<<<MROWS/4, 256>>>(os_gamma, os_beta);
    attn_hmma_kernel<<<dim3(GG/128, GG/128, NGRP), 256, SMEM_ATTN>>>();
    linkv_hmma_kernel<<<dim3(HHID/64, BB), 256, SMEM_LK>>>();
    fused_hmma_kernel<<<dim3(HHID/128, MROWS/128), 256, SMEM_ATTN>>>();

    // out = gated @ W_out + b_out + x  [8192, 1024]
    mm_bf16_kernel<256,2048,false,true,false><<<dim3(DD/256, MROWS/128), 256, SMEM_BIG>>>(
        gated_bf, woT, b_out, x, out, nullptr, DD);
}

// round 17
// speedup vs baseline: 1.0855x; 1.0266x over previous
#include <cuda_runtime.h>
#include <cuda_bf16.h>
#include <math.h>
#include <cstdint>

// Problem constants
#define BB   4
#define SEQ  2048
#define DD   1024
#define GG   256
#define QKD  128
#define HHID 2048
#define MROWS (BB*SEQ)        // 8192
#define NGRP  (MROWS/GG)      // 32
#define TWOH  (2*HHID)        // 4096

// -------- device scratch (no cudaMalloc allowed) --------
__device__ __nv_bfloat16 g_normed_bf[(size_t)MROWS*DD];    // 16 MB
__device__ __nv_bfloat16 g_h_bf[(size_t)MROWS*TWOH];       // 64 MB (v | gate)
__device__ float g_qk[(size_t)MROWS*QKD];                  // 4 MB
__device__ __nv_bfloat16 g_quadq_bf[(size_t)MROWS*QKD];    // 2 MB
__device__ __nv_bfloat16 g_quadk_bf[(size_t)MROWS*QKD];    // 2 MB
__device__ __nv_bfloat16 g_linq_bf[(size_t)MROWS*QKD];     // 2 MB
__device__ __nv_bfloat16 g_linkT_bf[(size_t)BB*QKD*SEQ];   // 2 MB  lin_k^T [b][d][n]
__device__ __nv_bfloat16 g_attn_bf[(size_t)NGRP*GG*GG];    // 4 MB
__device__ __nv_bfloat16 g_linkv_bf[(size_t)BB*QKD*HHID];  // 2 MB
__device__ __nv_bfloat16 g_gated_bf[(size_t)MROWS*HHID];   // 32 MB
__device__ __nv_bfloat16 g_whT[(size_t)TWOH*DD];           // 8 MB
__device__ __nv_bfloat16 g_wqkT[(size_t)QKD*DD];           // 0.25 MB
__device__ __nv_bfloat16 g_woT[(size_t)DD*HHID];           // 4 MB
__device__ float g_sin[SEQ*64];
__device__ float g_cos[SEQ*64];

// =================== PTX helpers (arch-portable: sm_80+ subset) ===================
__device__ __forceinline__ uint32_t smem_u32(const void* p) {
    uint32_t a;
    asm("{ .reg .u64 t; cvta.to.shared.u64 t, %1; cvt.u32.u64 %0, t; }" : "=r"(a) : "l"(p));
    return a;
}
#define SW128(o) ((o) ^ (((o) >> 3) & 0x70))   // 128B rows
#define SWZ256(o) ((o) ^ (((o) >> 4) & 0x70))  // 256B rows

__device__ __forceinline__ void cpa16(uint32_t dst, const void* src) {
    asm volatile("cp.async.cg.shared.global [%0], [%1], 16;" :: "r"(dst), "l"(src));
}
#define CP_COMMIT() asm volatile("cp.async.commit_group;" ::: "memory")
#define CP_WAIT(n)  asm volatile("cp.async.wait_group %0;" :: "n"(n) : "memory")

__device__ __forceinline__ void ldsm_x4(uint32_t* r, uint32_t addr) {
    asm volatile("ldmatrix.sync.aligned.m8n8.x4.shared.b16 {%0,%1,%2,%3}, [%4];"
                 : "=r"(r[0]), "=r"(r[1]), "=r"(r[2]), "=r"(r[3]) : "r"(addr));
}
__device__ __forceinline__ void ldsm_x2(uint32_t* r, uint32_t addr) {
    asm volatile("ldmatrix.sync.aligned.m8n8.x2.shared.b16 {%0,%1}, [%2];"
                 : "=r"(r[0]), "=r"(r[1]) : "r"(addr));
}
__device__ __forceinline__ void ldsm_x4t(uint32_t* r, uint32_t addr) {
    asm volatile("ldmatrix.sync.aligned.m8n8.x4.trans.shared.b16 {%0,%1,%2,%3}, [%4];"
                 : "=r"(r[0]), "=r"(r[1]), "=r"(r[2]), "=r"(r[3]) : "r"(addr));
}
__device__ __forceinline__ void mma_16816(float* c, const uint32_t* a, const uint32_t* b) {
    asm volatile(
        "mma.sync.aligned.m16n8k16.row.col.f32.bf16.bf16.f32 "
        "{%0,%1,%2,%3}, {%4,%5,%6,%7}, {%8,%9}, {%0,%1,%2,%3};"
        : "+f"(c[0]), "+f"(c[1]), "+f"(c[2]), "+f"(c[3])
        : "r"(a[0]), "r"(a[1]), "r"(a[2]), "r"(a[3]), "r"(b[0]), "r"(b[1]));
}
__device__ __forceinline__ void st_bf2(__nv_bfloat16* p, float a, float b) {
    *(__nv_bfloat162*)p = __floats2bfloat162_rn(a, b);
}

// ====== bf16 tensor-core GEMM: C[M,N] = A[M,K] @ Bt[N,K]^T ======
// CTA tile 128 x N_CTA, 8 warps (2x4), warp tile 64 x (N_CTA/4).
// 4-stage cp.async ring, two barriers/stage, B frags via ldmatrix.x4.
template<int N_CTA, int K_TOT, bool SILU_, bool RESID_, bool OUTBF_>
__global__ void __launch_bounds__(256, 1)
mm_bf16_kernel(const __nv_bfloat16* __restrict__ A,
               const __nv_bfloat16* __restrict__ Bt,
               const float* __restrict__ bias,
               const float* __restrict__ resid,
               float* __restrict__ Cf, __nv_bfloat16* __restrict__ Cb, int ldC)
{
    constexpr int STAGES = K_TOT / 64;
    constexpr int A_B    = 128 * 128;
    constexpr int B_B    = N_CTA * 128;
    constexpr int NI     = N_CTA / 32;
    constexpr int NQ     = NI / 2;
    constexpr int NBCH   = N_CTA / 32;
    extern __shared__ char smem[];
    const uint32_t aB = smem_u32(smem);
    const uint32_t bB = aB + 4 * A_B;

    const int tid = threadIdx.x, wid = tid >> 5, lane = tid & 31;
    const int m0 = blockIdx.y * 128, n0 = blockIdx.x * N_CTA;
    const int wm = (wid >> 2) * 64;
    const int wn = (wid & 3) * (N_CTA / 4);

    auto loadA = [&](int s, int buf) {
        uint32_t base = aB + buf * A_B;
        const __nv_bfloat16* src = A + (size_t)m0 * K_TOT + s * 64;
#pragma unroll
        for (int i = 0; i < 4; i++) {
            int c = tid + i * 256;
            int row = c >> 3, col = c & 7;
            cpa16(base + SW128(row * 128 + col * 16), src + (size_t)row * K_TOT + col * 8);
        }
    };
    auto loadB = [&](int s, int buf) {
        uint32_t base = bB + buf * B_B;
        const __nv_bfloat16* src = Bt + (size_t)n0 * K_TOT + s * 64;
#pragma unroll
        for (int i = 0; i < NBCH; i++) {
            int c = tid + i * 256;
            int row = c >> 3, col = c & 7;
            cpa16(base + SW128(row * 128 + col * 16), src + (size_t)row * K_TOT + col * 8);
        }
    };

    float acc[4][NI][4] = {};
    const int a_row = wm + (lane & 15);
    const int a_kof = (lane >> 4) * 8;
    const int bq_ro = (lane >> 4) * 8 + (lane & 7);
    const int bq_ko = ((lane >> 3) & 1) * 8;

    loadA(0, 0); loadB(0, 0); CP_COMMIT();
    loadA(1, 1); loadB(1, 1); CP_COMMIT();
    loadA(2, 2); loadB(2, 2); CP_COMMIT();

    for (int s = 0; s < STAGES; s++) {
        if (s + 3 < STAGES) {
            loadA(s + 3, (s + 3) & 3); loadB(s + 3, (s + 3) & 3);
            CP_COMMIT(); CP_WAIT(3);
        } else if (s + 2 < STAGES) CP_WAIT(2);
        else if (s + 1 < STAGES) CP_WAIT(1);
        else CP_WAIT(0);
        __syncthreads();
        const uint32_t abase = aB + (s & 3) * A_B;
        const uint32_t bbase = bB + (s & 3) * B_B;
#pragma unroll
        for (int ks = 0; ks < 4; ks++) {
            uint32_t af[4][4];
#pragma unroll
            for (int mi = 0; mi < 4; mi++)
                ldsm_x4(af[mi], abase + SW128((a_row + mi * 16) * 128 + (ks * 16 + a_kof) * 2));
            uint32_t bq[NQ][4];
#pragma unroll
            for (int nn = 0; nn < NQ; nn++) {
                int row = wn + nn * 16 + bq_ro;
                ldsm_x4(bq[nn], bbase + SW128(row * 128 + (ks * 16 + bq_ko) * 2));
            }
#pragma unroll
            for (int mi = 0; mi < 4; mi++)
#pragma unroll
                for (int nn = 0; nn < NQ; nn++) {
                    mma_16816(acc[mi][2 * nn + 0], af[mi], &bq[nn][0]);
                    mma_16816(acc[mi][2 * nn + 1], af[mi], &bq[nn][2]);
                }
        }
        __syncthreads();
    }

    const int er = m0 + wm + (lane >> 2);
    const int ec = n0 + wn + (lane & 3) * 2;
#pragma unroll
    for (int mi = 0; mi < 4; mi++)
#pragma unroll
        for (int ni = 0; ni < NI; ni++) {
            int col = ec + ni * 8;
#pragma unroll
            for (int half = 0; half < 2; half++) {
                int row = er + mi * 16 + half * 8;
                float v0 = acc[mi][ni][half * 2 + 0] + bias[col + 0];
                float v1 = acc[mi][ni][half * 2 + 1] + bias[col + 1];
                if (SILU_) { v0 = v0 / (1.0f + expf(-v0)); v1 = v1 / (1.0f + expf(-v1)); }
                if (RESID_) {
                    v0 += resid[(size_t)row * ldC + col + 0];
                    v1 += resid[(size_t)row * ldC + col + 1];
                }
                if (OUTBF_) st_bf2(Cb + (size_t)row * ldC + col, v0, v1);
                else { float2 o; o.x = v0; o.y = v1; *(float2*)(Cf + (size_t)row * ldC + col) = o; }
            }
        }
}

// ====== UNION: attn (blocks 0..127) + linkv (blocks 128..255) ======
// attn: attn = relu(quad_q @ quad_k^T / g)^2 -> bf16, 128x128 tile
// linkv: linkv[b,d,e] = sum_n lin_kT * v / SEQ, 128d x 64e tile
__global__ void __launch_bounds__(256)
attn_linkv_kernel()
{
    extern __shared__ char smem[];
    const uint32_t sB = smem_u32(smem);
    const int tid = threadIdx.x, wid = tid >> 5, lane = tid & 31;
    const int bid = blockIdx.x;

    if (bid < 128) {
        // ---------------- attn branch ----------------
        constexpr int TILE_B = 128 * 128;
        const uint32_t aB = sB;
        const uint32_t bB = sB + 2 * TILE_B;
        const int jx = bid & 1, iy = (bid >> 1) & 1, gid = bid >> 2;
        const int i0 = iy * 128, j0 = jx * 128;
        const int wm = (wid >> 2) * 64;
        const int wn = (wid & 3) * 32;

        const __nv_bfloat16* Aq = g_quadq_bf + ((size_t)gid * GG + i0) * QKD;
        const __nv_bfloat16* Bk = g_quadk_bf + ((size_t)gid * GG + j0) * QKD;

        auto loadT = [&](const __nv_bfloat16* src, uint32_t base, int s) {
            const __nv_bfloat16* p = src + s * 64;
#pragma unroll
            for (int i = 0; i < 4; i++) {
                int c = tid + i * 256;
                int row = c >> 3, col = c & 7;
                cpa16(base + SW128(row * 128 + col * 16), p + (size_t)row * QKD + col * 8);
            }
        };

        float acc[4][4][4] = {};
        const int a_row = wm + (lane & 15);
        const int a_kof = (lane >> 4) * 8;
        const int b_row = wn + (lane & 7);
        const int b_kof = ((lane >> 3) & 1) * 8;

        loadT(Aq, aB, 0); loadT(Bk, bB, 0); CP_COMMIT();
        for (int s = 0; s < 2; s++) {
            if (s + 1 < 2) {
                loadT(Aq, aB + TILE_B, 1); loadT(Bk, bB + TILE_B, 1);
                CP_COMMIT(); CP_WAIT(1);
            } else CP_WAIT(0);
            __syncthreads();
            const uint32_t abase = aB + s * TILE_B;
            const uint32_t bbase = bB + s * TILE_B;
#pragma unroll
            for (int ks = 0; ks < 4; ks++) {
                uint32_t af[4][4];
#pragma unroll
                for (int mi = 0; mi < 4; mi++)
                    ldsm_x4(af[mi], abase + SW128((a_row + mi * 16) * 128 + (ks * 16 + a_kof) * 2));
                uint32_t bf[4][2];
#pragma unroll
                for (int ni = 0; ni < 4; ni++)
                    ldsm_x2(bf[ni], bbase + SW128((b_row + ni * 8) * 128 + (ks * 16 + b_kof) * 2));
#pragma unroll
                for (int mi = 0; mi < 4; mi++)
#pragma unroll
                    for (int ni = 0; ni < 4; ni++)
                        mma_16816(acc[mi][ni], af[mi], bf[ni]);
            }
            __syncthreads();
        }

        __nv_bfloat16* Cp = g_attn_bf + (size_t)gid * GG * GG;
        const int er = i0 + wm + (lane >> 2);
        const int ec = j0 + wn + (lane & 3) * 2;
#pragma unroll
        for (int mi = 0; mi < 4; mi++)
#pragma unroll
            for (int ni = 0; ni < 4; ni++) {
                int col = ec + ni * 8;
#pragma unroll
                for (int half = 0; half < 2; half++) {
                    int row = er + mi * 16 + half * 8;
                    float s0 = fmaxf(acc[mi][ni][half * 2 + 0] * (1.0f / GG), 0.0f);
                    float s1 = fmaxf(acc[mi][ni][half * 2 + 1] * (1.0f / GG), 0.0f);
                    st_bf2(Cp + (size_t)row * GG + col, s0 * s0, s1 * s1);
                }
            }
    } else {
        // ---------------- linkv branch ----------------
        constexpr int A_B = 128 * 128;
        constexpr int B_B = 64 * 128;
        const uint32_t aB = sB;
        const uint32_t bB = sB + 2 * A_B;
        const int lb = bid - 128;
        const int b  = lb >> 5;          // 0..3
        const int e0 = (lb & 31) * 64;   // 0..1984
        const int wm = (wid & 3) * 32;
        const int wn = (wid >> 2) * 32;

        auto loadA = [&](int s, int buf) {
            uint32_t base = aB + buf * A_B;
            const __nv_bfloat16* src = g_linkT_bf + (size_t)b * QKD * SEQ + s * 64;
#pragma unroll
            for (int i = 0; i < 4; i++) {
                int c = tid + i * 256;
                int row = c >> 3, col = c & 7;
                cpa16(base + SW128(row * 128 + col * 16), src + (size_t)row * SEQ + col * 8);
            }
        };
        auto loadB = [&](int s, int buf) {
            uint32_t base = bB + buf * B_B;
            const __nv_bfloat16* src = g_h_bf + ((size_t)(b * SEQ + s * 64)) * TWOH + e0;
#pragma unroll
            for (int i = 0; i < 2; i++) {
                int c = tid + i * 256;
                int row = c >> 3, col = c & 7;
                cpa16(base + SW128(row * 128 + col * 16), src + (size_t)row * TWOH + col * 8);
            }
        };

        float acc[2][4][4] = {};
        const int a_row = wm + (lane & 15);
        const int a_kof = (lane >> 4) * 8;
        const int bt_k  = lane & 15;
        const int bt_n  = ((lane >> 4) & 1) * 8;

        loadA(0, 0); loadB(0, 0); CP_COMMIT();
        for (int s = 0; s < SEQ / 64; s++) {
            if (s + 1 < SEQ / 64) {
                loadA(s + 1, (s + 1) & 1); loadB(s + 1, (s + 1) & 1);
                CP_COMMIT(); CP_WAIT(1);
            } else CP_WAIT(0);
            __syncthreads();
            const uint32_t abase = aB + (s & 1) * A_B;
            const uint32_t bbase = bB + (s & 1) * B_B;
#pragma unroll
            for (int ks = 0; ks < 4; ks++) {
                uint32_t af[2][4];
#pragma unroll
                for (int mi = 0; mi < 2; mi++)
                    ldsm_x4(af[mi], abase + SW128((a_row + mi * 16) * 128 + (ks * 16 + a_kof) * 2));
                uint32_t bt[2][4];
#pragma unroll
                for (int g = 0; g < 2; g++)
                    ldsm_x4t(bt[g], bbase + SW128((ks * 16 + bt_k) * 128 + (wn + g * 16 + bt_n) * 2));
#pragma unroll
                for (int mi = 0; mi < 2; mi++)
#pragma unroll
                    for (int g = 0; g < 2; g++) {
                        mma_16816(acc[mi][g * 2 + 0], af[mi], &bt[g][0]);
                        mma_16816(acc[mi][g * 2 + 1], af[mi], &bt[g][2]);
                    }
            }
            __syncthreads();
        }

        __nv_bfloat16* Cp = g_linkv_bf + (size_t)b * QKD * HHID;
        const int er = wm + (lane >> 2);
        const int ec = e0 + wn + (lane & 3) * 2;
#pragma unroll
        for (int mi = 0; mi < 2; mi++)
#pragma unroll
            for (int ni = 0; ni < 4; ni++) {
                int col = ec + ni * 8;
#pragma unroll
                for (int half = 0; half < 2; half++) {
                    int row = er + mi * 16 + half * 8;
                    st_bf2(Cp + (size_t)row * HHID + col,
                           acc[mi][ni][half * 2 + 0] * (1.0f / SEQ),
                           acc[mi][ni][half * 2 + 1] * (1.0f / SEQ));
                }
            }
    }
}

// ====== fused HMMA: gated = gate * (attn@v + lin_q@lin_kv)  (128p x 128e tile) ======
__global__ void __launch_bounds__(256)
fused_hmma_kernel()
{
    constexpr int TILE_B = 128 * 128;
    extern __shared__ char smem[];
    const uint32_t aB = smem_u32(smem);
    const uint32_t bB = aB + 2 * TILE_B;

    const int tid = threadIdx.x, wid = tid >> 5, lane = tid & 31;
    const int p0 = blockIdx.y * 128, e0 = blockIdx.x * 128;
    const int gid = p0 >> 8, b = p0 >> 11, i0 = p0 & 255;
    const int wm = (wid >> 2) * 64;
    const int wn = (wid & 3) * 32;

    auto loadStage = [&](int s, int buf) {
        uint32_t abase = aB + buf * TILE_B;
        uint32_t bbase = bB + buf * TILE_B;
        if (s < 4) {
            const __nv_bfloat16* asrc = g_attn_bf + (size_t)gid * GG * GG + (size_t)i0 * GG + s * 64;
#pragma unroll
            for (int i = 0; i < 4; i++) {
                int c = tid + i * 256;
                int row = c >> 3, col = c & 7;
                cpa16(abase + SW128(row * 128 + col * 16), asrc + (size_t)row * GG + col * 8);
            }
            const __nv_bfloat16* bsrc = g_h_bf + ((size_t)(gid * GG + s * 64)) * TWOH + e0;
#pragma unroll
            for (int i = 0; i < 4; i++) {
                int c = tid + i * 256;
                int row = c >> 4, col = c & 15;
                cpa16(bbase + SWZ256(row * 256 + col * 16), bsrc + (size_t)row * TWOH + col * 8);
            }
        } else {
            int s2 = s - 4;
            const __nv_bfloat16* asrc = g_linq_bf + (size_t)p0 * QKD + s2 * 64;
#pragma unroll
            for (int i = 0; i < 4; i++) {
                int c = tid + i * 256;
                int row = c >> 3, col = c & 7;
                cpa16(abase + SW128(row * 128 + col * 16), asrc + (size_t)row * QKD + col * 8);
            }
            const __nv_bfloat16* bsrc = g_linkv_bf + (size_t)b * QKD * HHID + (size_t)(s2 * 64) * HHID + e0;
#pragma unroll
            for (int i = 0; i < 4; i++) {
                int c = tid + i * 256;
                int row = c >> 4, col = c & 15;
                cpa16(bbase + SWZ256(row * 256 + col * 16), bsrc + (size_t)row * HHID + col * 8);
            }
        }
    };

    float acc[4][4][4] = {};
    const int a_row = wm + (lane & 15);
    const int a_kof = (lane >> 4) * 8;
    const int bt_k  = lane & 15;
    const int bt_n  = ((lane >> 4) & 1) * 8;

    loadStage(0, 0); CP_COMMIT();
    for (int s = 0; s < 6; s++) {
        if (s + 1 < 6) { loadStage(s + 1, (s + 1) & 1); CP_COMMIT(); CP_WAIT(1); }
        else CP_WAIT(0);
        __syncthreads();
        const uint32_t abase = aB + (s & 1) * TILE_B;
        const uint32_t bbase = bB + (s & 1) * TILE_B;
#pragma unroll
        for (int ks = 0; ks < 4; ks++) {
            uint32_t af[4][4];
#pragma unroll
            for (int mi = 0; mi < 4; mi++)
                ldsm_x4(af[mi], abase + SW128((a_row + mi * 16) * 128 + (ks * 16 + a_kof) * 2));
            uint32_t bt[2][4];
#pragma unroll
            for (int g = 0; g < 2; g++)
                ldsm_x4t(bt[g], bbase + SWZ256((ks * 16 + bt_k) * 256 + (wn + g * 16 + bt_n) * 2));
#pragma unroll
            for (int mi = 0; mi < 4; mi++)
#pragma unroll
                for (int g = 0; g < 2; g++) {
                    mma_16816(acc[mi][g * 2 + 0], af[mi], &bt[g][0]);
                    mma_16816(acc[mi][g * 2 + 1], af[mi], &bt[g][2]);
                }
        }
        __syncthreads();
    }

    const int er = p0 + wm + (lane >> 2);
    const int ec = e0 + wn + (lane & 3) * 2;
#pragma unroll
    for (int mi = 0; mi < 4; mi++)
#pragma unroll
        for (int ni = 0; ni < 4; ni++) {
            int col = ec + ni * 8;
#pragma unroll
            for (int half = 0; half < 2; half++) {
                int row = er + mi * 16 + half * 8;
                __nv_bfloat162 g2 = *(const __nv_bfloat162*)(g_h_bf + (size_t)row * TWOH + HHID + col);
                st_bf2(g_gated_bf + (size_t)row * HHID + col,
                       __bfloat162float(g2.x) * acc[mi][ni][half * 2 + 0],
                       __bfloat162float(g2.y) * acc[mi][ni][half * 2 + 1]);
            }
        }
}

// ====== UNION prep kernel: 3 weight transposes + rope tables + LayerNorm ======
// block ranges (all 256 threads):
//   [0, 4096)        : W_hidden transpose  (nx = TWOH/32 = 128)
//   [4096, 4224)     : W_qk transpose      (nx = QKD/32 = 4)
//   [4224, 6272)     : W_out transpose     (nx = DD/32 = 32)
//   [6272, 6784)     : rope tables         (j = idx%64, chunk = idx/64)
//   [6784, 14976)    : LayerNorm rows
#define PB_WH   4096
#define PB_WQK  128
#define PB_WO   2048
#define PB_ROPE 512
#define PB_LN   MROWS
#define PREP_BLOCKS (PB_WH + PB_WQK + PB_WO + PB_ROPE + PB_LN)

__device__ __forceinline__ void transpose_tile(const float* __restrict__ in,
                                               __nv_bfloat16* __restrict__ out,
                                               int R, int Cc, int bx, int by, int tid,
                                               float (*t)[33]) {
    int c0 = bx * 32, r0 = by * 32;
    int x = tid & 31, y = tid >> 5;   // 32 x 8
#pragma unroll
    for (int i = 0; i < 32; i += 8)
        t[y + i][x] = in[(size_t)(r0 + y + i) * Cc + c0 + x];
    __syncthreads();
#pragma unroll
    for (int i = 0; i < 32; i += 8)
        out[(size_t)(c0 + y + i) * R + r0 + x] = __float2bfloat16(t[x][y + i]);
}

__global__ void __launch_bounds__(256)
prep_all_kernel(const float* __restrict__ x,
                const float* __restrict__ ln_g,
                const float* __restrict__ ln_b,
                const float* __restrict__ W_hidden,
                const float* __restrict__ W_qk,
                const float* __restrict__ W_out)
{
    __shared__ float tbuf[32][33];
    __shared__ float red[8];
    __shared__ float bcast;
    const int tid = threadIdx.x;
    int idx = blockIdx.x;

    if (idx < PB_WH) {
        transpose_tile(W_hidden, g_whT, DD, TWOH, idx % 128, idx / 128, tid, tbuf);
        return;
    }
    idx -= PB_WH;
    if (idx < PB_WQK) {
        transpose_tile(W_qk, g_wqkT, DD, QKD, idx % 4, idx / 4, tid, tbuf);
        return;
    }
    idx -= PB_WQK;
    if (idx < PB_WO) {
        transpose_tile(W_out, g_woT, HHID, DD, idx % 32, idx / 32, tid, tbuf);
        return;
    }
    idx -= PB_WO;
    if (idx < PB_ROPE) {
        int j = idx & 63, chunk = idx >> 6;
        if (tid == 0) bcast = (float)pow(10000.0, (double)j / 64.0);
        __syncthreads();
        float invf = bcast;
        int n = chunk * 256 + tid;
        float ang = (float)n * invf;
        g_sin[n*64 + j] = sinf(ang);
        g_cos[n*64 + j] = cosf(ang);
        return;
    }
    idx -= PB_ROPE;
    {
        // LayerNorm row
        int row = idx, t = tid;
        const float* xr = x + (size_t)row * DD;
        float v[4]; float s = 0.f;
#pragma unroll
        for (int c = 0; c < 4; c++) { v[c] = xr[t + 256*c]; s += v[c]; }
        int lane = t & 31, w = t >> 5;
#pragma unroll
        for (int o = 16; o; o >>= 1) s += __shfl_xor_sync(~0u, s, o);
        if (lane == 0) red[w] = s;
        __syncthreads();
        if (t == 0) { float tot = 0; for (int i = 0; i < 8; i++) tot += red[i]; bcast = tot / DD; }
        __syncthreads();
        float mu = bcast;
        float s2 = 0.f;
#pragma unroll
        for (int c = 0; c < 4; c++) { float d = v[c] - mu; s2 += d * d; }
#pragma unroll
        for (int o = 16; o; o >>= 1) s2 += __shfl_xor_sync(~0u, s2, o);
        __syncthreads();
        if (lane == 0) red[w] = s2;
        __syncthreads();
        if (t == 0) { float tot = 0; for (int i = 0; i < 8; i++) tot += red[i];
                      bcast = 1.0f / sqrtf(tot / DD + 1e-5f); }
        __syncthreads();
        float rstd = bcast;
        __nv_bfloat16* out = g_normed_bf + (size_t)row * DD;
#pragma unroll
        for (int c = 0; c < 4; c++) {
            int d = t + 256*c;
            out[d] = __float2bfloat16((v[c] - mu) * rstd * ln_g[d] + ln_b[d]);
        }
    }
}

// -------- OffsetScale + RoPE: all four heads -> bf16 --------
__global__ void rope_apply_kernel(const float* __restrict__ gamma,
                                  const float* __restrict__ beta) {
    int tid = threadIdx.x;
    int tok = blockIdx.x * 4 + (tid >> 6);
    int j   = tid & 63;
    int n   = tok & (SEQ - 1);
    int b   = tok >> 11;
    float v1 = g_qk[(size_t)tok * QKD + j];
    float v2 = g_qk[(size_t)tok * QKD + j + 64];
    float sn = g_sin[n*64 + j], cs = g_cos[n*64 + j];
    {
        float a1 = v1 * gamma[0*QKD + j]      + beta[0*QKD + j];
        float a2 = v2 * gamma[0*QKD + j + 64] + beta[0*QKD + j + 64];
        g_quadq_bf[(size_t)tok * QKD + j]      = __float2bfloat16(a1 * cs - a2 * sn);
        g_quadq_bf[(size_t)tok * QKD + j + 64] = __float2bfloat16(a2 * cs + a1 * sn);
    }
    {
        float a1 = v1 * gamma[2*QKD + j]      + beta[2*QKD + j];
        float a2 = v2 * gamma[2*QKD + j + 64] + beta[2*QKD + j + 64];
        g_quadk_bf[(size_t)tok * QKD + j]      = __float2bfloat16(a1 * cs - a2 * sn);
        g_quadk_bf[(size_t)tok * QKD + j + 64] = __float2bfloat16(a2 * cs + a1 * sn);
    }
    {
        float a1 = v1 * gamma[1*QKD + j]      + beta[1*QKD + j];
        float a2 = v2 * gamma[1*QKD + j + 64] + beta[1*QKD + j + 64];
        g_linq_bf[(size_t)tok * QKD + j]      = __float2bfloat16(a1 * cs - a2 * sn);
        g_linq_bf[(size_t)tok * QKD + j + 64] = __float2bfloat16(a2 * cs + a1 * sn);
    }
    {
        float a1 = v1 * gamma[3*QKD + j]      + beta[3*QKD + j];
        float a2 = v2 * gamma[3*QKD + j + 64] + beta[3*QKD + j + 64];
        __nv_bfloat16* base = g_linkT_bf + (size_t)b * QKD * SEQ;
        base[(size_t)j * SEQ + n]        = __float2bfloat16(a1 * cs - a2 * sn);
        base[(size_t)(j + 64) * SEQ + n] = __float2bfloat16(a2 * cs + a1 * sn);
    }
}

// ---------------------------------------------------------------------------
extern "C" void kernel_launch(void* const* d_in, const int* in_sizes, int n_in,
                              void* d_out, int out_size) {
    const float* x        = (const float*)d_in[0];
    const float* ln_g     = (const float*)d_in[1];
    const float* ln_b     = (const float*)d_in[2];
    const float* W_hidden = (const float*)d_in[3];
    const float* b_hidden = (const float*)d_in[4];
    const float* W_qk     = (const float*)d_in[5];
    const float* b_qk     = (const float*)d_in[6];
    const float* os_gamma = (const float*)d_in[7];
    const float* os_beta  = (const float*)d_in[8];
    const float* W_out    = (const float*)d_in[9];
    const float* b_out    = (const float*)d_in[10];
    float* out = (float*)d_out;

    __nv_bfloat16 *normed_bf, *whT, *wqkT, *woT, *gated_bf, *h_bf;
    float *qk;
    cudaGetSymbolAddress((void**)&normed_bf, g_normed_bf);
    cudaGetSymbolAddress((void**)&whT,  g_whT);
    cudaGetSymbolAddress((void**)&wqkT, g_wqkT);
    cudaGetSymbolAddress((void**)&woT,  g_woT);
    cudaGetSymbolAddress((void**)&gated_bf, g_gated_bf);
    cudaGetSymbolAddress((void**)&h_bf, g_h_bf);
    cudaGetSymbolAddress((void**)&qk, g_qk);

    const int SMEM_BIG   = 4 * (16384 + 32768);   // 196608 (N_CTA=256)
    const int SMEM_SMALL = 4 * (16384 + 16384);   // 131072 (N_CTA=128)
    const int SMEM_UNION = 4 * 128 * 128;         // 64 KB (attn needs 64K, linkv 48K)
    cudaFuncSetAttribute(mm_bf16_kernel<256,1024,true,false,true>,
                         cudaFuncAttributeMaxDynamicSharedMemorySize, SMEM_BIG);
    cudaFuncSetAttribute(mm_bf16_kernel<128,1024,true,false,false>,
                         cudaFuncAttributeMaxDynamicSharedMemorySize, SMEM_SMALL);
    cudaFuncSetAttribute(mm_bf16_kernel<256,2048,false,true,false>,
                         cudaFuncAttributeMaxDynamicSharedMemorySize, SMEM_BIG);
    cudaFuncSetAttribute(attn_linkv_kernel,
                         cudaFuncAttributeMaxDynamicSharedMemorySize, SMEM_UNION);
    cudaFuncSetAttribute(fused_hmma_kernel,
                         cudaFuncAttributeMaxDynamicSharedMemorySize, SMEM_UNION);

    // all prep in one launch: transposes + rope tables + LN
    prep_all_kernel<<<PREP_BLOCKS, 256>>>(x, ln_g, ln_b, W_hidden, W_qk, W_out);

    // h = silu(normed @ W_hidden + b) -> bf16 [8192, 4096]
    mm_bf16_kernel<256,1024,true,false,true><<<dim3(TWOH/256, MROWS/128), 256, SMEM_BIG>>>(
        normed_bf, whT, b_hidden, nullptr, nullptr, h_bf, TWOH);
    // qk = silu(normed @ W_qk + b) -> fp32 [8192, 128]
    mm_bf16_kernel<128,1024,true,false,false><<<dim3(QKD/128, MROWS/128), 256, SMEM_SMALL>>>(
        normed_bf, wqkT, b_qk, nullptr, qk, nullptr, QKD);

    rope_apply_kernel<<<MROWS/4, 256>>>(os_gamma, os_beta);
    attn_linkv_kernel<<<256, 256, SMEM_UNION>>>();
    fused_hmma_kernel<<<dim3(HHID/128, MROWS/128), 256, SMEM_UNION>>>();

    // out = gated @ W_out + b_out + x  [8192, 1024]
    mm_bf16_kernel<256,2048,false,true,false><<<dim3(DD/256, MROWS/128), 256, SMEM_BIG>>>(
        gated_bf, woT, b_out, x, out, nullptr, DD);
}